// round 14
// baseline (speedup 1.0000x reference)
#include <cuda_runtime.h>
#include <math_constants.h>

// ---------------------------------------------------------------------------
// APPM: 13-ratio sliding-window avg pooling (smem SAT) + 3-group greedy NMS
// (picks 2/3/2, IoU 0.25), batch 256.
//
// Round-14 = round-13 with the row2 rh bug fixed (rows 1024..1043 are ratio
// 11 = rh 28, not 40; row2_params now returns rh). Design: R6 thread-per-tile
// scoring with a fused per-row max cache (order-preserving uint keys,
// segmented warp-max + smem atomicMax), then row-pruned NMS picks:
//   ph1: rows with zero x-overlap vs the priors contribute cached rowmax ->
//        group lower bound LB (achievable).
//   ph2: rows with rowmax >= LB rescan exactly from the SAT (identical fp
//        expression -> bit-identical scores -> sound pruning; min-idx ties).
// Suppression is division-free: 5*inter > areaW + selarea (exact small ints
// in fp32 == reference IoU > 0.25).
//
// Output layout (float32):
//   [0,1792)               proposalN_indices  (256 x 7) as float
//   [1792,3584)            proposalN_windows_scores (256 x 7)
//   [3584, 3584+256*96981) window_scores (256 x 96981)
// ---------------------------------------------------------------------------

#define FEAT   112
#define SATN   113
#define SATP   116            // padded SAT row stride (multiple of 4)
#define NRAT   13
#define NBATCH 256
#define NTOTAL 96981
#define PROPN  7
#define NTH    1024
#define NROWS  1121
#define NEGINF (-CUDART_INF_F)

__host__ __device__ constexpr int cRH(int r) {
    constexpr int a[NRAT] = {16,12,20,24,20,28,32,24,40,28,40,28,36};
    return a[r];
}
__host__ __device__ constexpr int cRW(int r) {
    constexpr int a[NRAT] = {16,20,12,24,28,20,32,40,24,40,28,36,28};
    return a[r];
}
__host__ __device__ constexpr int cBASE(int r) {
    constexpr int a[NRAT+1] = {0,9409,18802,28195,36116,44021,51926,58487,
                               64984,71481,77686,83891,90436,96981};
    return a[r];
}
__host__ __device__ constexpr int cXO(int r) {
    constexpr int a[NRAT+1] = {0,97,198,291,380,473,558,639,728,801,886,959,1044,1121};
    return a[r];
}

// runtime-indexable copies for the compact (cold) NMS code
__constant__ int   d_RH[NRAT]   = {16,12,20,24,20,28,32,24,40,28,40,28,36};
__constant__ int   d_RW[NRAT]   = {16,20,12,24,28,20,32,40,24,40,28,36,28};
__constant__ int   d_BASE[NRAT] = {0,9409,18802,28195,36116,44021,51926,58487,
                                   64984,71481,77686,83891,90436};
__constant__ int   d_XO[NRAT+1] = {0,97,198,291,380,473,558,639,728,801,886,959,1044,1121};
// MUST equal 1.0f/(float)(rh*rw) bit-exactly (same IEEE single-op divide)
__constant__ float d_INV[NRAT]  = {1.0f/256.0f, 1.0f/240.0f, 1.0f/240.0f,
                                   1.0f/576.0f, 1.0f/560.0f, 1.0f/560.0f,
                                   1.0f/1024.0f, 1.0f/960.0f, 1.0f/960.0f,
                                   1.0f/1120.0f, 1.0f/1120.0f,
                                   1.0f/1008.0f, 1.0f/1008.0f};

// dynamic smem (floats): SAT[113*116] | RMAXu[1121 uint]
#define SMEM_FLOATS (SATN*SATP + NROWS)

// order-preserving float->uint key; canonicalize -0.0 so key order matches
// float equality exactly.
__device__ __forceinline__ unsigned fkey(float f) {
    unsigned u = __float_as_uint(f);
    u = (u == 0x80000000u) ? 0u : u;
    return (u & 0x80000000u) ? ~u : (u | 0x80000000u);
}

// warp-level pairwise merge (max score, min idx on tie); result in lane 0
__device__ __forceinline__ void wmerge(float& b, int& bi) {
    #pragma unroll
    for (int o = 16; o > 0; o >>= 1) {
        float os = __shfl_down_sync(0xffffffffu, b, o);
        int   oi = __shfl_down_sync(0xffffffffu, bi, o);
        if (os > b || (os == b && oi < bi)) { b = os; bi = oi; }
    }
}

// segmented warp max of `key` over contiguous equal-`seg` lane runs; segment
// leader does atomicMax into LBk[seg]. seg monotone over lanes; seg<0 inactive.
__device__ __forceinline__ void seg_atomic_max(
    unsigned key, int seg, unsigned* LBk, int lane)
{
    #pragma unroll
    for (int o = 1; o < 32; o <<= 1) {
        unsigned ok = __shfl_down_sync(0xffffffffu, key, o);
        int      os = __shfl_down_sync(0xffffffffu, seg, o);
        if (os == seg && ok > key) key = ok;
    }
    int ps = __shfl_up_sync(0xffffffffu, seg, 1);
    if (seg >= 0 && (lane == 0 || ps != seg)) atomicMax(&LBk[seg], key);
}

// decode a winning window index into its box + area (lane0 only)
__device__ __forceinline__ void decode_box(int bidx, float* box, float* sa) {
    int rh = cRH(0), rw = cRW(0), bb = 0;
    #pragma unroll
    for (int r = 1; r < NRAT; r++)
        if (bidx >= cBASE(r)) { rh = cRH(r); rw = cRW(r); bb = cBASE(r); }
    int off = bidx - bb;
    int nc = SATN - rw;
    int xi = off / nc, yi = off - xi * nc;
    float x0u = (float)(4 * xi - 1), y0u = (float)(4 * yi - 1);
    float cx0 = fmaxf(x0u, 0.0f), cy0 = fmaxf(y0u, 0.0f);
    float cx1 = x0u + (float)(4 * rh);
    float cy1 = y0u + (float)(4 * rw);
    box[0] = cx0; box[1] = cy0; box[2] = cx1; box[3] = cy1;
    *sa = (cx1 - cx0 + 1.0f) * (cy1 - cy0 + 1.0f);
}

// params for a second-batch row (rows 1024..1120 -> ratio 11 or 12 only).
// FIX (R14): returns rh too (ratio 11 is rh=28; R13 wrongly used 40).
__device__ __forceinline__ void row2_params(
    int row, int& xi, int& rh, int& rw, int& nc, int& base, int& R_,
    float& inv, float& x0, float& x1)
{
    int r = (row >= 1044) ? 12 : 11;
    rh = d_RH[r]; rw = d_RW[r];
    xi = row - d_XO[r];
    nc = SATN - rw; base = d_BASE[r]; R_ = rh * SATP; inv = d_INV[r];
    float x0u = (float)(4 * xi - 1);
    x0 = fmaxf(x0u, 0.0f);
    x1 = x0u + (float)(4 * rh);
}

// ---------------------------------------------------------------------------
// phase 2: exact re-evaluation of one row (with np-prior suppression).
// Single compact instantiation (runtime loops).
// ---------------------------------------------------------------------------
__device__ __noinline__ void ph2_scan(
    const float* __restrict__ S,
    int mxi, int mrh, int mrw, int mnc, int mbase, int mR, float minv,
    float mx0, float mx1,
    const float* pb,      // priors: pb[p*4 + {x0,y0,x1,y1}]
    const float* pa,      // prior areas
    int np,
    float& s_best, int& i_best)
{
    float frh = (float)(4 * mrh), frw = (float)(4 * mrw);
    float ax = (mxi == 0) ? frh : frh + 1.0f;
    float w5[2] = {0.0f, 0.0f};
    for (int p = 0; p < np; p++)
        w5[p] = 5.0f * fmaxf(fminf(mx1, pb[p*4+2]) - fmaxf(mx0, pb[p*4+0]) + 1.0f, 0.0f);
    int a0 = mxi * SATP;
    int rowoff = mbase + mxi * mnc;
    #pragma unroll 1
    for (int yi = 0; yi < mnc; yi++) {
        int a = a0 + yi;
        // EXACT same expression/order as the scoring pass
        float s = (S[a + mR + mrw] - S[a + mrw] - S[a + mR] + S[a]) * minv;
        float ay = (yi == 0) ? frw : frw + 1.0f;
        float y0u = (float)(4 * yi - 1);
        float y0 = fmaxf(y0u, 0.0f), y1 = y0u + frw;
        bool sup = false;
        for (int p = 0; p < np; p++) {
            float hy = fmaxf(fminf(y1, pb[p*4+3]) - fmaxf(y0, pb[p*4+1]) + 1.0f, 0.0f);
            sup = sup || (w5[p] * hy > fmaf(ax, ay, pa[p]));
        }
        if (!sup && s > s_best) { s_best = s; i_best = rowoff + yi; } // asc -> min idx
    }
}

__global__ void __launch_bounds__(NTH, 2)
appm_kernel(const float* __restrict__ x, float* __restrict__ out)
{
    extern __shared__ float SH[];
    float*    S     = SH;                        // SATN * SATP padded SAT
    unsigned* RMAXu = (unsigned*)(SH + SATN * SATP);   // per-row max key

    __shared__ float    red_s[3][32];
    __shared__ int      red_i[3][32];
    __shared__ float    pbox[3][2][4];           // per-group priors
    __shared__ float    parea[3][2];
    __shared__ unsigned LBk[3];

    const int tid  = threadIdx.x;
    const int b    = blockIdx.x;
    const int lane = tid & 31;
    const int warp = tid >> 5;

    const float* __restrict__ xb = x + (size_t)b * (FEAT * FEAT);

    // ---- (1) SAT build + cache init ----------------------------------------
    for (int k = tid; k < SATN * SATP; k += NTH) {
        int i = k / SATP;
        int j = k - i * SATP;
        float v = 0.0f;
        if (i > 0 && j > 0 && j < SATN) v = xb[(i - 1) * FEAT + (j - 1)];
        S[k] = v;
    }
    for (int k = tid; k < NROWS; k += NTH) RMAXu[k] = 0u;
    if (tid < 3) LBk[tid] = 0u;
    __syncthreads();
    if (tid < SATN) {                     // row prefix
        float acc = 0.0f;
        float* row = S + tid * SATP;
        #pragma unroll 4
        for (int j = 1; j < SATN; j++) { acc += row[j]; row[j] = acc; }
    }
    __syncthreads();
    if (tid < SATN) {                     // column prefix (coalesced)
        float acc = 0.0f;
        #pragma unroll 4
        for (int i = 1; i < SATN; i++) {
            acc += S[i * SATP + tid];
            S[i * SATP + tid] = acc;
        }
    }
    __syncthreads();

    // ---- (2) scoring (R6 structure) + fused per-row max cache --------------
    float* ws = out + 2 * (NBATCH * PROPN) + (size_t)b * NTOTAL;

    #pragma unroll
    for (int r = 0; r < NRAT; r++) {
        const int rh = cRH(r), rw = cRW(r);
        const int nr = SATN - rh, nc = SATN - rw;
        const int nq = (nc + 3) >> 2;     // nc % 4 == 1: last tile = 1 window
        const int ntile = nr * nq;
        const float inv = 1.0f / (float)(rh * rw);
        const int base = cBASE(r);
        const int R_ = rh * SATP;
        const int rowb = cXO(r);
        float* wsr = ws + base;
        #pragma unroll 1
        for (int t0 = 0; t0 < ntile; t0 += NTH) {
            int t = t0 + tid;
            unsigned key = 0u;
            int row = -1;
            if (t < ntile) {
                int xi = t / nq;          // nq const -> mul/shift
                int q  = t - xi * nq;
                int yi = q << 2;
                int a  = xi * SATP + yi;  // 16B-aligned
                float4 v0 = *(const float4*)(S + a);
                float4 v1 = *(const float4*)(S + a + rw);
                float4 v2 = *(const float4*)(S + a + R_);
                float4 v3 = *(const float4*)(S + a + R_ + rw);
                float s0 = (v3.x - v1.x - v2.x + v0.x) * inv;
                float s1 = (v3.y - v1.y - v2.y + v0.y) * inv;
                float s2 = (v3.z - v1.z - v2.z + v0.z) * inv;
                float s3 = (v3.w - v1.w - v2.w + v0.w) * inv;
                int off = xi * nc + yi;
                bool full = (q != nq - 1);
                wsr[off] = s0;
                if (full) {
                    wsr[off + 1] = s1;
                    wsr[off + 2] = s2;
                    wsr[off + 3] = s3;
                }
                float m1 = full ? s1 : NEGINF;
                float m2 = full ? s2 : NEGINF;
                float m3 = full ? s3 : NEGINF;
                float m = fmaxf(fmaxf(s0, m1), fmaxf(m2, m3));
                key = fkey(m);
                row = rowb + xi;
            }
            seg_atomic_max(key, row, RMAXu, lane);
        }
    }
    __syncthreads();   // RMAXu complete; ws stores done (never re-read)

    // ---- (3) primary row (row1 = tid) parameters, resolved once ------------
    int mg, mxi, mrh, mrw, mnc, mbase, mR;
    float minv, mx0, mx1;
    {
        int r = 0;
        #pragma unroll 1
        for (int k = 1; k < NRAT; k++) if (tid >= d_XO[k]) r = k;
        mg = (r < 3) ? 0 : ((r < 6) ? 1 : 2);
        mxi = tid - d_XO[r];
        mrh = d_RH[r]; mrw = d_RW[r];
        mnc = SATN - mrw; mbase = d_BASE[r]; mR = mrh * SATP;
        minv = d_INV[r];
        float x0u = (float)(4 * mxi - 1);
        mx0 = fmaxf(x0u, 0.0f);
        mx1 = x0u + (float)(4 * mrh);
    }
    const int row2 = tid + NTH;               // second-batch row (group 2)
    const bool has2 = (row2 < NROWS);

    float cs[3]; int ci[3];

    // ======================= Round A: pick0 (np = 0) ========================
    {   // ph1: LB = max rowmax per group (row1 + row2)
        seg_atomic_max(RMAXu[tid], mg, LBk, lane);
        seg_atomic_max(has2 ? RMAXu[row2] : 0u, has2 ? 2 : -1, LBk, lane);
        __syncthreads();
        // ph2: rescan rows achieving the max
        float sb = NEGINF; int ib = 0x7fffffff;
        if (RMAXu[tid] >= LBk[mg])
            ph2_scan(S, mxi, mrh, mrw, mnc, mbase, mR, minv, mx0, mx1,
                     &pbox[0][0][0], &parea[0][0], 0, sb, ib);
        float sb2 = NEGINF; int ib2 = 0x7fffffff;
        if (has2 && RMAXu[row2] >= LBk[2]) {
            int xi2, rh2, rw2, nc2, base2, R2; float inv2, x20, x21;
            row2_params(row2, xi2, rh2, rw2, nc2, base2, R2, inv2, x20, x21);
            ph2_scan(S, xi2, rh2, rw2, nc2, base2, R2, inv2, x20, x21,
                     &pbox[0][0][0], &parea[0][0], 0, sb2, ib2);
        }
        #pragma unroll
        for (int g = 0; g < 3; g++) {
            cs[g] = (mg == g) ? sb : NEGINF;
            ci[g] = (mg == g) ? ib : 0x7fffffff;
        }
        if (sb2 > cs[2]) { cs[2] = sb2; ci[2] = ib2; }  // row2 idx > row1 idx
        #pragma unroll
        for (int g = 0; g < 3; g++) wmerge(cs[g], ci[g]);
        if (lane == 0)
            #pragma unroll
            for (int g = 0; g < 3; g++) { red_s[g][warp] = cs[g]; red_i[g][warp] = ci[g]; }
        __syncthreads();
        if (warp == 0) {
            float bb[3]; int ii[3];
            #pragma unroll
            for (int g = 0; g < 3; g++) { bb[g] = red_s[g][lane]; ii[g] = red_i[g][lane]; wmerge(bb[g], ii[g]); }
            if (lane == 0) {
                const int slot[3] = {0, 2, 5};
                #pragma unroll
                for (int g = 0; g < 3; g++) {
                    out[b * PROPN + slot[g]] = (float)ii[g];
                    out[NBATCH * PROPN + b * PROPN + slot[g]] = bb[g];
                    decode_box(ii[g], &pbox[g][0][0], &parea[g][0]);
                    LBk[g] = 0u;                    // reset for round B
                }
            }
        }
        __syncthreads();
    }

    // ======================= Round B: pick1 (np = 1) ========================
    {   // ph1: zero-x-overlap rows vs prior 0
        unsigned k = 0u;
        {
            float ov = fmaxf(fminf(mx1, pbox[mg][0][2]) - fmaxf(mx0, pbox[mg][0][0]) + 1.0f, 0.0f);
            if (ov == 0.0f) k = RMAXu[tid];
        }
        seg_atomic_max(k, mg, LBk, lane);
        unsigned k2 = 0u;
        int xi2, rh2, rw2, nc2, base2, R2;
        float inv2, x20 = 0.0f, x21 = 0.0f;
        if (has2) {
            row2_params(row2, xi2, rh2, rw2, nc2, base2, R2, inv2, x20, x21);
            float ov = fmaxf(fminf(x21, pbox[2][0][2]) - fmaxf(x20, pbox[2][0][0]) + 1.0f, 0.0f);
            if (ov == 0.0f) k2 = RMAXu[row2];
        }
        seg_atomic_max(k2, has2 ? 2 : -1, LBk, lane);
        __syncthreads();
        float sb = NEGINF; int ib = 0x7fffffff;
        if (RMAXu[tid] >= LBk[mg])
            ph2_scan(S, mxi, mrh, mrw, mnc, mbase, mR, minv, mx0, mx1,
                     &pbox[mg][0][0], &parea[mg][0], 1, sb, ib);
        float sb2 = NEGINF; int ib2 = 0x7fffffff;
        if (has2 && RMAXu[row2] >= LBk[2])
            ph2_scan(S, xi2, rh2, rw2, nc2, base2, R2, inv2, x20, x21,
                     &pbox[2][0][0], &parea[2][0], 1, sb2, ib2);
        #pragma unroll
        for (int g = 0; g < 3; g++) {
            cs[g] = (mg == g) ? sb : NEGINF;
            ci[g] = (mg == g) ? ib : 0x7fffffff;
        }
        if (sb2 > cs[2]) { cs[2] = sb2; ci[2] = ib2; }
        #pragma unroll
        for (int g = 0; g < 3; g++) wmerge(cs[g], ci[g]);
        if (lane == 0)
            #pragma unroll
            for (int g = 0; g < 3; g++) { red_s[g][warp] = cs[g]; red_i[g][warp] = ci[g]; }
        __syncthreads();
        if (warp == 0) {
            float bb[3]; int ii[3];
            #pragma unroll
            for (int g = 0; g < 3; g++) { bb[g] = red_s[g][lane]; ii[g] = red_i[g][lane]; wmerge(bb[g], ii[g]); }
            if (lane == 0) {
                const int slot[3] = {1, 3, 6};
                #pragma unroll
                for (int g = 0; g < 3; g++) {
                    out[b * PROPN + slot[g]] = (float)ii[g];
                    out[NBATCH * PROPN + b * PROPN + slot[g]] = bb[g];
                }
                decode_box(ii[1], &pbox[1][1][0], &parea[1][1]);
                LBk[1] = 0u;                        // reset for round C
            }
        }
        __syncthreads();
    }

    // ==================== Round C: g1 pick2 (np = 2) ========================
    {   // group 1 rows are 291..557 -> all covered by row1; no row2 handling
        int seg = (mg == 1) ? 1 : -1;
        unsigned k = 0u;
        if (seg == 1) {
            float ov = fmaxf(fminf(mx1, pbox[1][0][2]) - fmaxf(mx0, pbox[1][0][0]) + 1.0f, 0.0f)
                     + fmaxf(fminf(mx1, pbox[1][1][2]) - fmaxf(mx0, pbox[1][1][0]) + 1.0f, 0.0f);
            if (ov == 0.0f) k = RMAXu[tid];
        }
        seg_atomic_max(k, seg, LBk, lane);
        __syncthreads();
        float sb = NEGINF; int ib = 0x7fffffff;
        if (seg == 1 && RMAXu[tid] >= LBk[1])
            ph2_scan(S, mxi, mrh, mrw, mnc, mbase, mR, minv, mx0, mx1,
                     &pbox[1][0][0], &parea[1][0], 2, sb, ib);
        wmerge(sb, ib);
        if (lane == 0) { red_s[0][warp] = sb; red_i[0][warp] = ib; }
        __syncthreads();
        if (warp == 0) {
            sb = red_s[0][lane]; ib = red_i[0][lane];
            wmerge(sb, ib);
            if (lane == 0) {
                out[b * PROPN + 4] = (float)ib;
                out[NBATCH * PROPN + b * PROPN + 4] = sb;
            }
        }
    }
}

extern "C" void kernel_launch(void* const* d_in, const int* in_sizes, int n_in,
                              void* d_out, int out_size) {
    const float* x = (const float*)d_in[0];
    float* out = (float*)d_out;
    (void)in_sizes; (void)n_in; (void)out_size;

    const int smem = SMEM_FLOATS * (int)sizeof(float);  // 56916 B
    cudaFuncSetAttribute(appm_kernel, cudaFuncAttributeMaxDynamicSharedMemorySize, smem);
    appm_kernel<<<NBATCH, NTH, smem>>>(x, out);
}

// round 15
// speedup vs baseline: 1.5580x; 1.5580x over previous
#include <cuda_runtime.h>
#include <math_constants.h>

// ---------------------------------------------------------------------------
// APPM: 13-ratio sliding-window avg pooling (smem SAT) + 3-group greedy NMS
// (picks 2/3/2, IoU 0.25), batch 256.
//
// Round-15 = round-6 (best validated) + two micro-opts:
//  (1) NMS-scan argmax uses plain strict '>' (per-thread visit order is
//      ascending index, so min-index ties are preserved without the extra
//      tie-break compare; cross-thread ties handled in wmerge as before).
//  (2) SAT row/column prefix scans parallelized 4x via 4 segments of 28
//      (452 active threads, two-level scan with carry fix-up).
// Everything else identical to round-6: thread-per-tile float4 scoring with
// fused pick0, P=1 NMS scans recomputing scores from the smem SAT, P=2 scan
// via LDG, division-free suppression (5*inter > areaW + selarea).
//
// Output layout (float32):
//   [0,1792)               proposalN_indices  (256 x 7) as float
//   [1792,3584)            proposalN_windows_scores (256 x 7)
//   [3584, 3584+256*96981) window_scores (256 x 96981)
// ---------------------------------------------------------------------------

#define FEAT   112
#define SATN   113
#define SATP   116            // padded SAT row stride (multiple of 4)
#define NRAT   13
#define NBATCH 256
#define NTOTAL 96981
#define PROPN  7
#define NTH    1024
#define NYS    1160           // per-slot hy-table floats (padded nc summed)
#define NEGINF (-CUDART_INF_F)

__host__ __device__ constexpr int cRH(int r) {
    constexpr int a[NRAT] = {16,12,20,24,20,28,32,24,40,28,40,28,36};
    return a[r];
}
__host__ __device__ constexpr int cRW(int r) {
    constexpr int a[NRAT] = {16,20,12,24,28,20,32,40,24,40,28,36,28};
    return a[r];
}
__host__ __device__ constexpr int cBASE(int r) {
    constexpr int a[NRAT+1] = {0,9409,18802,28195,36116,44021,51926,58487,
                               64984,71481,77686,83891,90436,96981};
    return a[r];
}
// prefix sums of padded-to-4 nc (nc = 113-RW)
__host__ __device__ constexpr int cYQ(int r) {
    constexpr int a[NRAT] = {0,100,196,300,392,480,576,660,736,828,904,992,1072};
    return a[r];
}

// dynamic smem (floats): SAT[113*116] | HYS[2*NYS]
#define SMEM_FLOATS (SATN*SATP + 2*NYS)

// warp-level pairwise merge (max score, min idx on tie)
__device__ __forceinline__ void wmerge(float& b, int& bi) {
    #pragma unroll
    for (int o = 16; o > 0; o >>= 1) {
        float os = __shfl_down_sync(0xffffffffu, b, o);
        int   oi = __shfl_down_sync(0xffffffffu, bi, o);
        if (os > b || (os == b && oi < bi)) { b = os; bi = oi; }
    }
}

// decode a winning window index into its box + area (lane0 only)
__device__ __forceinline__ void decode_box(int bidx, float* box, float* sa) {
    int rh = cRH(0), rw = cRW(0), bb = 0;
    #pragma unroll
    for (int r = 1; r < NRAT; r++)
        if (bidx >= cBASE(r)) { rh = cRH(r); rw = cRW(r); bb = cBASE(r); }
    int off = bidx - bb;
    int nc = SATN - rw;
    int xi = off / nc, yi = off - xi * nc;
    float x0u = (float)(4 * xi - 1), y0u = (float)(4 * yi - 1);
    float cx0 = fmaxf(x0u, 0.0f), cy0 = fmaxf(y0u, 0.0f);
    float cx1 = x0u + (float)(4 * rh);
    float cy1 = y0u + (float)(4 * rw);
    box[0] = cx0; box[1] = cy0; box[2] = cx1; box[3] = cy1;
    *sa = (cx1 - cx0 + 1.0f) * (cy1 - cy0 + 1.0f);
}

// fill hy table (full yi range incl. border yi=0; zero pad) for [R0,R1)
template<int R0, int R1>
__device__ __forceinline__ void fill_hys(
    int slot, int tid, float* HYS, const float* box)
{
    float by0 = box[1], by1 = box[3];
    #pragma unroll
    for (int r = R0; r < R1; r++) {
        const int rw = cRW(r);
        const int nc = SATN - rw;
        const int ncp = (nc + 3) & ~3;
        if (tid < ncp) {
            float h = 0.0f;
            if (tid < nc) {
                float y0u = (float)(4 * tid - 1);
                float y0 = fmaxf(y0u, 0.0f);
                float y1 = y0u + (float)(4 * rw);
                h = fmaxf(fminf(y1, by1) - fmaxf(y0, by0) + 1.0f, 0.0f);
            }
            HYS[slot * NYS + cYQ(r) + tid] = h;
        }
    }
}

// ---------------------------------------------------------------------------
// NMS scan, ratios [R0,R1). RECOMP: scores recomputed from SAT via float4
// (P=1 path, no gmem); else scalar LDG from ws (P=2 path, fewer regs).
// Suppress iff 5*inter > areaW + selarea (exact ints in fp32 == IoU>0.25).
// Argmax uses plain strict '>' (per-thread ascending visit order keeps
// min-index ties).
// ---------------------------------------------------------------------------
template<int R0, int R1, int P, bool RECOMP>
__device__ __forceinline__ void nms_scan(
    const float* __restrict__ S, const float* __restrict__ ws,
    const float* __restrict__ HYS,
    float bx0a, float bx1a, float saA,
    float bx0b, float bx1b, float saB,
    int tid, float& best, int& bidx)
{
    #pragma unroll
    for (int r = R0; r < R1; r++) {
        const int rh = cRH(r), rw = cRW(r);
        const int nr = SATN - rh, nc = SATN - rw;
        const int nq = (nc + 3) >> 2;          // nc % 4 == 1: last tile = 1 win
        const int ntile = nr * nq;
        const int base = cBASE(r);
        const int R_ = rh * SATP;
        const float inv = 1.0f / (float)(rh * rw);
        const float frh  = (float)(4 * rh),     frw  = (float)(4 * rw);
        const float frh1 = frh + 1.0f,          frw1 = frw + 1.0f;
        const float* hys0 = HYS + cYQ(r);
        const float* hys1 = HYS + NYS + cYQ(r);
        const float* wsr = ws + base;

        #pragma unroll 1
        for (int t = tid; t < ntile; t += NTH) {
            int xi = t / nq;                   // nq const -> mul/shift
            int q  = t - xi * nq;
            int yq = q << 2;
            bool full = (q != nq - 1);
            float s0, s1, s2, s3;
            if constexpr (RECOMP) {
                int a = xi * SATP + yq;        // 16B-aligned
                float4 v0 = *(const float4*)(S + a);
                float4 v1 = *(const float4*)(S + a + rw);
                float4 v2 = *(const float4*)(S + a + R_);
                float4 v3 = *(const float4*)(S + a + R_ + rw);
                s0 = (v3.x - v1.x - v2.x + v0.x) * inv;
                s1 = (v3.y - v1.y - v2.y + v0.y) * inv;
                s2 = (v3.z - v1.z - v2.z + v0.z) * inv;
                s3 = (v3.w - v1.w - v2.w + v0.w) * inv;
            } else {
                int o = xi * nc + yq;
                s0 = wsr[o];
                s1 = full ? wsr[o + 1] : NEGINF;
                s2 = full ? wsr[o + 2] : NEGINF;
                s3 = full ? wsr[o + 3] : NEGINF;
            }
            float x0u = (float)(4 * xi - 1);
            float x0 = fmaxf(x0u, 0.0f), x1 = x0u + frh;
            float ax = (xi == 0) ? frh : frh1;
            float w5a = 5.0f * fmaxf(fminf(x1, bx1a) - fmaxf(x0, bx0a) + 1.0f, 0.0f);
            float rhsa  = fmaf(ax, frw1, saA);
            float rhsa0 = fmaf(ax, frw,  saA);     // yi == 0 (ay = frw)
            float4 h4 = *(const float4*)(hys0 + yq);
            bool k0 = (w5a * h4.x <= ((yq == 0) ? rhsa0 : rhsa));
            bool k1 = (w5a * h4.y <= rhsa);
            bool k2 = (w5a * h4.z <= rhsa);
            bool k3 = (w5a * h4.w <= rhsa);
            if constexpr (P >= 2) {
                float w5b = 5.0f * fmaxf(fminf(x1, bx1b) - fmaxf(x0, bx0b) + 1.0f, 0.0f);
                float rhsb  = fmaf(ax, frw1, saB);
                float rhsb0 = fmaf(ax, frw,  saB);
                float4 g4 = *(const float4*)(hys1 + yq);
                k0 &= (w5b * g4.x <= ((yq == 0) ? rhsb0 : rhsb));
                k1 &= (w5b * g4.y <= rhsb);
                k2 &= (w5b * g4.z <= rhsb);
                k3 &= (w5b * g4.w <= rhsb);
            }
            int off = base + xi * nc + yq;
            // plain strict '>' — per-thread ascending order keeps min index
            if (k0 &&         s0 > best) { best = s0; bidx = off;     }
            if (k1 && full && s1 > best) { best = s1; bidx = off + 1; }
            if (k2 && full && s2 > best) { best = s2; bidx = off + 2; }
            if (k3 && full && s3 > best) { best = s3; bidx = off + 3; }
        }
    }
}

__global__ void __launch_bounds__(NTH, 2)
appm_kernel(const float* __restrict__ x, float* __restrict__ out)
{
    extern __shared__ float SH[];
    float* S   = SH;                    // SATN * SATP padded SAT
    float* HYS = SH + SATN * SATP;      // 2 slots * NYS

    __shared__ float red_s[3][32];
    __shared__ int   red_i[3][32];
    __shared__ float boxsm[4][4];       // pick0 g0/g1/g2, g1-pick1
    __shared__ float sarea[4];
    __shared__ float TOT[452];          // segment totals for 2-level prefixes

    const int tid  = threadIdx.x;
    const int b    = blockIdx.x;
    const int lane = tid & 31;
    const int warp = tid >> 5;

    const float* __restrict__ xb = x + (size_t)b * (FEAT * FEAT);

    // ---- (1) SAT build (padded stride 116; cols 113-115 stay zero) --------
    for (int k = tid; k < SATN * SATP; k += NTH) {
        int i = k / SATP;
        int j = k - i * SATP;
        float v = 0.0f;
        if (i > 0 && j > 0 && j < SATN) v = xb[(i - 1) * FEAT + (j - 1)];
        S[k] = v;
    }
    __syncthreads();

    // row prefix, 2-level: 113 rows x 4 segments of 28 cols (cols 1..112)
    if (tid < 452) {
        int r = tid >> 2, s = tid & 3;
        float* row = S + r * SATP;
        int j0 = 1 + s * 28;
        float acc = 0.0f;
        #pragma unroll
        for (int j = 0; j < 28; j++) { acc += row[j0 + j]; row[j0 + j] = acc; }
        TOT[tid] = acc;
    }
    __syncthreads();
    if (tid < 452) {
        int r = tid >> 2, s = tid & 3;
        if (s > 0) {
            float carry = TOT[(r << 2)];
            if (s > 1) carry += TOT[(r << 2) + 1];
            if (s > 2) carry += TOT[(r << 2) + 2];
            float* row = S + r * SATP;
            int j0 = 1 + s * 28;
            #pragma unroll
            for (int j = 0; j < 28; j++) row[j0 + j] += carry;
        }
    }
    __syncthreads();

    // column prefix, 2-level: 113 cols x 4 segments of 28 rows (rows 1..112)
    if (tid < 452) {
        int c = tid >> 2, s = tid & 3;
        int i0 = 1 + s * 28;
        float acc = 0.0f;
        #pragma unroll
        for (int i = 0; i < 28; i++) {
            acc += S[(i0 + i) * SATP + c];
            S[(i0 + i) * SATP + c] = acc;
        }
        TOT[tid] = acc;
    }
    __syncthreads();
    if (tid < 452) {
        int c = tid >> 2, s = tid & 3;
        if (s > 0) {
            float carry = TOT[(c << 2)];
            if (s > 1) carry += TOT[(c << 2) + 1];
            if (s > 2) carry += TOT[(c << 2) + 2];
            int i0 = 1 + s * 28;
            #pragma unroll
            for (int i = 0; i < 28; i++) S[(i0 + i) * SATP + c] += carry;
        }
    }
    __syncthreads();

    // ---- (2) window scores -> gmem via float4 SAT tiles, fused pick0 ------
    float* ws = out + 2 * (NBATCH * PROPN) + (size_t)b * NTOTAL;

    float bst[3] = {NEGINF, NEGINF, NEGINF};
    int   bix[3] = {0x7fffffff, 0x7fffffff, 0x7fffffff};

    #pragma unroll
    for (int r = 0; r < NRAT; r++) {
        const int rh = cRH(r), rw = cRW(r);
        const int nr = SATN - rh, nc = SATN - rw;
        const int nq = (nc + 3) >> 2;
        const int ntile = nr * nq;
        const float inv = 1.0f / (float)(rh * rw);
        const int base = cBASE(r);
        const int g = (r < 3) ? 0 : (r < 6) ? 1 : 2;
        const int R_ = rh * SATP;
        float* wsr = ws + base;
        #pragma unroll 1
        for (int t = tid; t < ntile; t += NTH) {
            int xi = t / nq;
            int q  = t - xi * nq;
            int yi = q << 2;
            int a  = xi * SATP + yi;    // 16B-aligned
            float4 v0 = *(const float4*)(S + a);
            float4 v1 = *(const float4*)(S + a + rw);
            float4 v2 = *(const float4*)(S + a + R_);
            float4 v3 = *(const float4*)(S + a + R_ + rw);
            float s0 = (v3.x - v1.x - v2.x + v0.x) * inv;
            float s1 = (v3.y - v1.y - v2.y + v0.y) * inv;
            float s2 = (v3.z - v1.z - v2.z + v0.z) * inv;
            float s3 = (v3.w - v1.w - v2.w + v0.w) * inv;
            int off = xi * nc + yi;
            if (q != nq - 1) {
                wsr[off]     = s0;
                wsr[off + 1] = s1;
                wsr[off + 2] = s2;
                wsr[off + 3] = s3;
                if (s0 > bst[g]) { bst[g] = s0; bix[g] = base + off; }
                if (s1 > bst[g]) { bst[g] = s1; bix[g] = base + off + 1; }
                if (s2 > bst[g]) { bst[g] = s2; bix[g] = base + off + 2; }
                if (s3 > bst[g]) { bst[g] = s3; bix[g] = base + off + 3; }
            } else {
                wsr[off] = s0;
                if (s0 > bst[g]) { bst[g] = s0; bix[g] = base + off; }
            }
        }
    }

    // ---- (3a) batched 3-way reduction: pick0 of each group ----------------
    {
        #pragma unroll
        for (int g = 0; g < 3; g++) wmerge(bst[g], bix[g]);
        if (lane == 0)
            #pragma unroll
            for (int g = 0; g < 3; g++) { red_s[g][warp] = bst[g]; red_i[g][warp] = bix[g]; }
        __syncthreads();   // also orders ws stores before NMS reads
        if (warp == 0) {
            float bb[3]; int ii[3];
            #pragma unroll
            for (int g = 0; g < 3; g++) { bb[g] = red_s[g][lane]; ii[g] = red_i[g][lane]; wmerge(bb[g], ii[g]); }
            if (lane == 0) {
                const int slot[3] = {0, 2, 5};
                #pragma unroll
                for (int g = 0; g < 3; g++) {
                    out[b * PROPN + slot[g]] = (float)ii[g];
                    out[NBATCH * PROPN + b * PROPN + slot[g]] = bb[g];
                    decode_box(ii[g], boxsm[g], &sarea[g]);
                }
            }
        }
        __syncthreads();
    }

    // ---- (3b) hy tables (slot 0) for all 3 groups' pick0 priors ------------
    fill_hys<0, 3>(0, tid, HYS, boxsm[0]);
    fill_hys<3, 6>(0, tid, HYS, boxsm[1]);
    fill_hys<6, 13>(0, tid, HYS, boxsm[2]);
    __syncthreads();

    // ---- (3c) pick1 scans (SAT recompute path, no gmem) --------------------
    float b0x0 = boxsm[0][0], b0x1 = boxsm[0][2];
    float b1x0 = boxsm[1][0], b1x1 = boxsm[1][2];
    float b2x0 = boxsm[2][0], b2x1 = boxsm[2][2];
    float sa0 = sarea[0], sa1g = sarea[1], sa2 = sarea[2];

    bst[0] = bst[1] = bst[2] = NEGINF;
    bix[0] = bix[1] = bix[2] = 0x7fffffff;
    nms_scan<0, 3, 1, true>(S, ws, HYS, b0x0, b0x1, sa0,
                            0, 0, 0, tid, bst[0], bix[0]);
    nms_scan<3, 6, 1, true>(S, ws, HYS, b1x0, b1x1, sa1g,
                            0, 0, 0, tid, bst[1], bix[1]);
    nms_scan<6, 13, 1, true>(S, ws, HYS, b2x0, b2x1, sa2,
                             0, 0, 0, tid, bst[2], bix[2]);

    // ---- (3d) batched reduction: pick1s; decode only g1's winner -----------
    {
        #pragma unroll
        for (int g = 0; g < 3; g++) wmerge(bst[g], bix[g]);
        if (lane == 0)
            #pragma unroll
            for (int g = 0; g < 3; g++) { red_s[g][warp] = bst[g]; red_i[g][warp] = bix[g]; }
        __syncthreads();
        if (warp == 0) {
            float bb[3]; int ii[3];
            #pragma unroll
            for (int g = 0; g < 3; g++) { bb[g] = red_s[g][lane]; ii[g] = red_i[g][lane]; wmerge(bb[g], ii[g]); }
            if (lane == 0) {
                const int slot[3] = {1, 3, 6};
                #pragma unroll
                for (int g = 0; g < 3; g++) {
                    out[b * PROPN + slot[g]] = (float)ii[g];
                    out[NBATCH * PROPN + b * PROPN + slot[g]] = bb[g];
                }
                decode_box(ii[1], boxsm[3], &sarea[3]);
            }
        }
        __syncthreads();
    }

    // ---- (3e) g1 pick2: slot-1 tables, 2-prior scan (LDG path) --------------
    fill_hys<3, 6>(1, tid, HYS, boxsm[3]);
    __syncthreads();
    float b3x0 = boxsm[3][0], b3x1 = boxsm[3][2];
    float nb = NEGINF; int ni = 0x7fffffff;
    nms_scan<3, 6, 2, false>(S, ws, HYS, b1x0, b1x1, sa1g,
                             b3x0, b3x1, sarea[3], tid, nb, ni);
    {
        wmerge(nb, ni);
        if (lane == 0) { red_s[0][warp] = nb; red_i[0][warp] = ni; }
        __syncthreads();
        if (warp == 0) {
            nb = red_s[0][lane]; ni = red_i[0][lane];
            wmerge(nb, ni);
            if (lane == 0) {
                out[b * PROPN + 4] = (float)ni;
                out[NBATCH * PROPN + b * PROPN + 4] = nb;
            }
        }
    }
}

extern "C" void kernel_launch(void* const* d_in, const int* in_sizes, int n_in,
                              void* d_out, int out_size) {
    const float* x = (const float*)d_in[0];
    float* out = (float*)d_out;
    (void)in_sizes; (void)n_in; (void)out_size;

    const int smem = SMEM_FLOATS * (int)sizeof(float);  // 61712 B
    cudaFuncSetAttribute(appm_kernel, cudaFuncAttributeMaxDynamicSharedMemorySize, smem);
    appm_kernel<<<NBATCH, NTH, smem>>>(x, out);
}

// round 16
// speedup vs baseline: 1.5591x; 1.0008x over previous
#include <cuda_runtime.h>
#include <math_constants.h>

// ---------------------------------------------------------------------------
// APPM: 13-ratio sliding-window avg pooling (smem SAT) + 3-group greedy NMS
// (picks 2/3/2, IoU 0.25), batch 256.
//
// Round-16 = round-15 + P=2 scan switched from scalar-LDG to the SAT-RECOMP
// path (the LDG branch is removed entirely): all NMS scans now recompute
// scores from the smem SAT via float4 (no gmem latency anywhere in NMS).
// Retains R15's parallel 2-level SAT prefix scans and plain strict-'>' argmax
// (per-thread ascending visit order preserves min-index ties).
// Suppression stays division-free: 5*inter > areaW + selarea (exact small
// ints in fp32 == reference IoU > 0.25).
//
// Output layout (float32):
//   [0,1792)               proposalN_indices  (256 x 7) as float
//   [1792,3584)            proposalN_windows_scores (256 x 7)
//   [3584, 3584+256*96981) window_scores (256 x 96981)
// ---------------------------------------------------------------------------

#define FEAT   112
#define SATN   113
#define SATP   116            // padded SAT row stride (multiple of 4)
#define NRAT   13
#define NBATCH 256
#define NTOTAL 96981
#define PROPN  7
#define NTH    1024
#define NYS    1160           // per-slot hy-table floats (padded nc summed)
#define NEGINF (-CUDART_INF_F)

__host__ __device__ constexpr int cRH(int r) {
    constexpr int a[NRAT] = {16,12,20,24,20,28,32,24,40,28,40,28,36};
    return a[r];
}
__host__ __device__ constexpr int cRW(int r) {
    constexpr int a[NRAT] = {16,20,12,24,28,20,32,40,24,40,28,36,28};
    return a[r];
}
__host__ __device__ constexpr int cBASE(int r) {
    constexpr int a[NRAT+1] = {0,9409,18802,28195,36116,44021,51926,58487,
                               64984,71481,77686,83891,90436,96981};
    return a[r];
}
// prefix sums of padded-to-4 nc (nc = 113-RW)
__host__ __device__ constexpr int cYQ(int r) {
    constexpr int a[NRAT] = {0,100,196,300,392,480,576,660,736,828,904,992,1072};
    return a[r];
}

// dynamic smem (floats): SAT[113*116] | HYS[2*NYS]
#define SMEM_FLOATS (SATN*SATP + 2*NYS)

// warp-level pairwise merge (max score, min idx on tie)
__device__ __forceinline__ void wmerge(float& b, int& bi) {
    #pragma unroll
    for (int o = 16; o > 0; o >>= 1) {
        float os = __shfl_down_sync(0xffffffffu, b, o);
        int   oi = __shfl_down_sync(0xffffffffu, bi, o);
        if (os > b || (os == b && oi < bi)) { b = os; bi = oi; }
    }
}

// decode a winning window index into its box + area (lane0 only)
__device__ __forceinline__ void decode_box(int bidx, float* box, float* sa) {
    int rh = cRH(0), rw = cRW(0), bb = 0;
    #pragma unroll
    for (int r = 1; r < NRAT; r++)
        if (bidx >= cBASE(r)) { rh = cRH(r); rw = cRW(r); bb = cBASE(r); }
    int off = bidx - bb;
    int nc = SATN - rw;
    int xi = off / nc, yi = off - xi * nc;
    float x0u = (float)(4 * xi - 1), y0u = (float)(4 * yi - 1);
    float cx0 = fmaxf(x0u, 0.0f), cy0 = fmaxf(y0u, 0.0f);
    float cx1 = x0u + (float)(4 * rh);
    float cy1 = y0u + (float)(4 * rw);
    box[0] = cx0; box[1] = cy0; box[2] = cx1; box[3] = cy1;
    *sa = (cx1 - cx0 + 1.0f) * (cy1 - cy0 + 1.0f);
}

// fill hy table (full yi range incl. border yi=0; zero pad) for [R0,R1)
template<int R0, int R1>
__device__ __forceinline__ void fill_hys(
    int slot, int tid, float* HYS, const float* box)
{
    float by0 = box[1], by1 = box[3];
    #pragma unroll
    for (int r = R0; r < R1; r++) {
        const int rw = cRW(r);
        const int nc = SATN - rw;
        const int ncp = (nc + 3) & ~3;
        if (tid < ncp) {
            float h = 0.0f;
            if (tid < nc) {
                float y0u = (float)(4 * tid - 1);
                float y0 = fmaxf(y0u, 0.0f);
                float y1 = y0u + (float)(4 * rw);
                h = fmaxf(fminf(y1, by1) - fmaxf(y0, by0) + 1.0f, 0.0f);
            }
            HYS[slot * NYS + cYQ(r) + tid] = h;
        }
    }
}

// ---------------------------------------------------------------------------
// NMS scan, ratios [R0,R1), P priors (1 or 2). Scores recomputed from the
// smem SAT via float4 (bit-identical to the scoring pass). Suppress iff
// 5*inter > areaW + selarea (exact ints in fp32 == reference IoU>0.25).
// Argmax via plain strict '>' (ascending per-thread order keeps min index).
// ---------------------------------------------------------------------------
template<int R0, int R1, int P>
__device__ __forceinline__ void nms_scan(
    const float* __restrict__ S, const float* __restrict__ HYS,
    float bx0a, float bx1a, float saA,
    float bx0b, float bx1b, float saB,
    int tid, float& best, int& bidx)
{
    #pragma unroll
    for (int r = R0; r < R1; r++) {
        const int rh = cRH(r), rw = cRW(r);
        const int nr = SATN - rh, nc = SATN - rw;
        const int nq = (nc + 3) >> 2;          // nc % 4 == 1: last tile = 1 win
        const int ntile = nr * nq;
        const int base = cBASE(r);
        const int R_ = rh * SATP;
        const float inv = 1.0f / (float)(rh * rw);
        const float frh  = (float)(4 * rh),     frw  = (float)(4 * rw);
        const float frh1 = frh + 1.0f,          frw1 = frw + 1.0f;
        const float* hys0 = HYS + cYQ(r);
        const float* hys1 = HYS + NYS + cYQ(r);

        #pragma unroll 1
        for (int t = tid; t < ntile; t += NTH) {
            int xi = t / nq;                   // nq const -> mul/shift
            int q  = t - xi * nq;
            int yq = q << 2;
            bool full = (q != nq - 1);
            int a = xi * SATP + yq;            // 16B-aligned
            float4 v0 = *(const float4*)(S + a);
            float4 v1 = *(const float4*)(S + a + rw);
            float4 v2 = *(const float4*)(S + a + R_);
            float4 v3 = *(const float4*)(S + a + R_ + rw);
            float s0 = (v3.x - v1.x - v2.x + v0.x) * inv;
            float s1 = (v3.y - v1.y - v2.y + v0.y) * inv;
            float s2 = (v3.z - v1.z - v2.z + v0.z) * inv;
            float s3 = (v3.w - v1.w - v2.w + v0.w) * inv;
            float x0u = (float)(4 * xi - 1);
            float x0 = fmaxf(x0u, 0.0f), x1 = x0u + frh;
            float ax = (xi == 0) ? frh : frh1;
            float w5a = 5.0f * fmaxf(fminf(x1, bx1a) - fmaxf(x0, bx0a) + 1.0f, 0.0f);
            float rhsa  = fmaf(ax, frw1, saA);
            float rhsa0 = fmaf(ax, frw,  saA);     // yi == 0 (ay = frw)
            float4 h4 = *(const float4*)(hys0 + yq);
            bool k0 = (w5a * h4.x <= ((yq == 0) ? rhsa0 : rhsa));
            bool k1 = (w5a * h4.y <= rhsa);
            bool k2 = (w5a * h4.z <= rhsa);
            bool k3 = (w5a * h4.w <= rhsa);
            if constexpr (P >= 2) {
                float w5b = 5.0f * fmaxf(fminf(x1, bx1b) - fmaxf(x0, bx0b) + 1.0f, 0.0f);
                float rhsb  = fmaf(ax, frw1, saB);
                float rhsb0 = fmaf(ax, frw,  saB);
                float4 g4 = *(const float4*)(hys1 + yq);
                k0 &= (w5b * g4.x <= ((yq == 0) ? rhsb0 : rhsb));
                k1 &= (w5b * g4.y <= rhsb);
                k2 &= (w5b * g4.z <= rhsb);
                k3 &= (w5b * g4.w <= rhsb);
            }
            int off = base + xi * nc + yq;
            // plain strict '>' — per-thread ascending order keeps min index
            if (k0 &&         s0 > best) { best = s0; bidx = off;     }
            if (k1 && full && s1 > best) { best = s1; bidx = off + 1; }
            if (k2 && full && s2 > best) { best = s2; bidx = off + 2; }
            if (k3 && full && s3 > best) { best = s3; bidx = off + 3; }
        }
    }
}

__global__ void __launch_bounds__(NTH, 2)
appm_kernel(const float* __restrict__ x, float* __restrict__ out)
{
    extern __shared__ float SH[];
    float* S   = SH;                    // SATN * SATP padded SAT
    float* HYS = SH + SATN * SATP;      // 2 slots * NYS

    __shared__ float red_s[3][32];
    __shared__ int   red_i[3][32];
    __shared__ float boxsm[4][4];       // pick0 g0/g1/g2, g1-pick1
    __shared__ float sarea[4];
    __shared__ float TOT[452];          // segment totals for 2-level prefixes

    const int tid  = threadIdx.x;
    const int b    = blockIdx.x;
    const int lane = tid & 31;
    const int warp = tid >> 5;

    const float* __restrict__ xb = x + (size_t)b * (FEAT * FEAT);

    // ---- (1) SAT build (padded stride 116; cols 113-115 stay zero) --------
    for (int k = tid; k < SATN * SATP; k += NTH) {
        int i = k / SATP;
        int j = k - i * SATP;
        float v = 0.0f;
        if (i > 0 && j > 0 && j < SATN) v = xb[(i - 1) * FEAT + (j - 1)];
        S[k] = v;
    }
    __syncthreads();

    // row prefix, 2-level: 113 rows x 4 segments of 28 cols (cols 1..112)
    if (tid < 452) {
        int r = tid >> 2, s = tid & 3;
        float* row = S + r * SATP;
        int j0 = 1 + s * 28;
        float acc = 0.0f;
        #pragma unroll
        for (int j = 0; j < 28; j++) { acc += row[j0 + j]; row[j0 + j] = acc; }
        TOT[tid] = acc;
    }
    __syncthreads();
    if (tid < 452) {
        int r = tid >> 2, s = tid & 3;
        if (s > 0) {
            float carry = TOT[(r << 2)];
            if (s > 1) carry += TOT[(r << 2) + 1];
            if (s > 2) carry += TOT[(r << 2) + 2];
            float* row = S + r * SATP;
            int j0 = 1 + s * 28;
            #pragma unroll
            for (int j = 0; j < 28; j++) row[j0 + j] += carry;
        }
    }
    __syncthreads();

    // column prefix, 2-level: 113 cols x 4 segments of 28 rows (rows 1..112)
    if (tid < 452) {
        int c = tid >> 2, s = tid & 3;
        int i0 = 1 + s * 28;
        float acc = 0.0f;
        #pragma unroll
        for (int i = 0; i < 28; i++) {
            acc += S[(i0 + i) * SATP + c];
            S[(i0 + i) * SATP + c] = acc;
        }
        TOT[tid] = acc;
    }
    __syncthreads();
    if (tid < 452) {
        int c = tid >> 2, s = tid & 3;
        if (s > 0) {
            float carry = TOT[(c << 2)];
            if (s > 1) carry += TOT[(c << 2) + 1];
            if (s > 2) carry += TOT[(c << 2) + 2];
            int i0 = 1 + s * 28;
            #pragma unroll
            for (int i = 0; i < 28; i++) S[(i0 + i) * SATP + c] += carry;
        }
    }
    __syncthreads();

    // ---- (2) window scores -> gmem via float4 SAT tiles, fused pick0 ------
    float* ws = out + 2 * (NBATCH * PROPN) + (size_t)b * NTOTAL;

    float bst[3] = {NEGINF, NEGINF, NEGINF};
    int   bix[3] = {0x7fffffff, 0x7fffffff, 0x7fffffff};

    #pragma unroll
    for (int r = 0; r < NRAT; r++) {
        const int rh = cRH(r), rw = cRW(r);
        const int nr = SATN - rh, nc = SATN - rw;
        const int nq = (nc + 3) >> 2;
        const int ntile = nr * nq;
        const float inv = 1.0f / (float)(rh * rw);
        const int base = cBASE(r);
        const int g = (r < 3) ? 0 : (r < 6) ? 1 : 2;
        const int R_ = rh * SATP;
        float* wsr = ws + base;
        #pragma unroll 1
        for (int t = tid; t < ntile; t += NTH) {
            int xi = t / nq;
            int q  = t - xi * nq;
            int yi = q << 2;
            int a  = xi * SATP + yi;    // 16B-aligned
            float4 v0 = *(const float4*)(S + a);
            float4 v1 = *(const float4*)(S + a + rw);
            float4 v2 = *(const float4*)(S + a + R_);
            float4 v3 = *(const float4*)(S + a + R_ + rw);
            float s0 = (v3.x - v1.x - v2.x + v0.x) * inv;
            float s1 = (v3.y - v1.y - v2.y + v0.y) * inv;
            float s2 = (v3.z - v1.z - v2.z + v0.z) * inv;
            float s3 = (v3.w - v1.w - v2.w + v0.w) * inv;
            int off = xi * nc + yi;
            if (q != nq - 1) {
                wsr[off]     = s0;
                wsr[off + 1] = s1;
                wsr[off + 2] = s2;
                wsr[off + 3] = s3;
                if (s0 > bst[g]) { bst[g] = s0; bix[g] = base + off; }
                if (s1 > bst[g]) { bst[g] = s1; bix[g] = base + off + 1; }
                if (s2 > bst[g]) { bst[g] = s2; bix[g] = base + off + 2; }
                if (s3 > bst[g]) { bst[g] = s3; bix[g] = base + off + 3; }
            } else {
                wsr[off] = s0;
                if (s0 > bst[g]) { bst[g] = s0; bix[g] = base + off; }
            }
        }
    }

    // ---- (3a) batched 3-way reduction: pick0 of each group ----------------
    {
        #pragma unroll
        for (int g = 0; g < 3; g++) wmerge(bst[g], bix[g]);
        if (lane == 0)
            #pragma unroll
            for (int g = 0; g < 3; g++) { red_s[g][warp] = bst[g]; red_i[g][warp] = bix[g]; }
        __syncthreads();
        if (warp == 0) {
            float bb[3]; int ii[3];
            #pragma unroll
            for (int g = 0; g < 3; g++) { bb[g] = red_s[g][lane]; ii[g] = red_i[g][lane]; wmerge(bb[g], ii[g]); }
            if (lane == 0) {
                const int slot[3] = {0, 2, 5};
                #pragma unroll
                for (int g = 0; g < 3; g++) {
                    out[b * PROPN + slot[g]] = (float)ii[g];
                    out[NBATCH * PROPN + b * PROPN + slot[g]] = bb[g];
                    decode_box(ii[g], boxsm[g], &sarea[g]);
                }
            }
        }
        __syncthreads();
    }

    // ---- (3b) hy tables (slot 0) for all 3 groups' pick0 priors ------------
    fill_hys<0, 3>(0, tid, HYS, boxsm[0]);
    fill_hys<3, 6>(0, tid, HYS, boxsm[1]);
    fill_hys<6, 13>(0, tid, HYS, boxsm[2]);
    __syncthreads();

    // ---- (3c) pick1 scans (SAT recompute path, no gmem) --------------------
    float b0x0 = boxsm[0][0], b0x1 = boxsm[0][2];
    float b1x0 = boxsm[1][0], b1x1 = boxsm[1][2];
    float b2x0 = boxsm[2][0], b2x1 = boxsm[2][2];
    float sa0 = sarea[0], sa1g = sarea[1], sa2 = sarea[2];

    bst[0] = bst[1] = bst[2] = NEGINF;
    bix[0] = bix[1] = bix[2] = 0x7fffffff;
    nms_scan<0, 3, 1>(S, HYS, b0x0, b0x1, sa0,  0, 0, 0, tid, bst[0], bix[0]);
    nms_scan<3, 6, 1>(S, HYS, b1x0, b1x1, sa1g, 0, 0, 0, tid, bst[1], bix[1]);
    nms_scan<6, 13, 1>(S, HYS, b2x0, b2x1, sa2, 0, 0, 0, tid, bst[2], bix[2]);

    // ---- (3d) batched reduction: pick1s; decode only g1's winner -----------
    {
        #pragma unroll
        for (int g = 0; g < 3; g++) wmerge(bst[g], bix[g]);
        if (lane == 0)
            #pragma unroll
            for (int g = 0; g < 3; g++) { red_s[g][warp] = bst[g]; red_i[g][warp] = bix[g]; }
        __syncthreads();
        if (warp == 0) {
            float bb[3]; int ii[3];
            #pragma unroll
            for (int g = 0; g < 3; g++) { bb[g] = red_s[g][lane]; ii[g] = red_i[g][lane]; wmerge(bb[g], ii[g]); }
            if (lane == 0) {
                const int slot[3] = {1, 3, 6};
                #pragma unroll
                for (int g = 0; g < 3; g++) {
                    out[b * PROPN + slot[g]] = (float)ii[g];
                    out[NBATCH * PROPN + b * PROPN + slot[g]] = bb[g];
                }
                decode_box(ii[1], boxsm[3], &sarea[3]);
            }
        }
        __syncthreads();
    }

    // ---- (3e) g1 pick2: slot-1 tables, 2-prior scan (now RECOMP too) --------
    fill_hys<3, 6>(1, tid, HYS, boxsm[3]);
    __syncthreads();
    float b3x0 = boxsm[3][0], b3x1 = boxsm[3][2];
    float nb = NEGINF; int ni = 0x7fffffff;
    nms_scan<3, 6, 2>(S, HYS, b1x0, b1x1, sa1g,
                      b3x0, b3x1, sarea[3], tid, nb, ni);
    {
        wmerge(nb, ni);
        if (lane == 0) { red_s[0][warp] = nb; red_i[0][warp] = ni; }
        __syncthreads();
        if (warp == 0) {
            nb = red_s[0][lane]; ni = red_i[0][lane];
            wmerge(nb, ni);
            if (lane == 0) {
                out[b * PROPN + 4] = (float)ni;
                out[NBATCH * PROPN + b * PROPN + 4] = nb;
            }
        }
    }
}

extern "C" void kernel_launch(void* const* d_in, const int* in_sizes, int n_in,
                              void* d_out, int out_size) {
    const float* x = (const float*)d_in[0];
    float* out = (float*)d_out;
    (void)in_sizes; (void)n_in; (void)out_size;

    const int smem = SMEM_FLOATS * (int)sizeof(float);  // 61712 B
    cudaFuncSetAttribute(appm_kernel, cudaFuncAttributeMaxDynamicSharedMemorySize, smem);
    appm_kernel<<<NBATCH, NTH, smem>>>(x, out);
}